// round 15
// baseline (speedup 1.0000x reference)
#include <cuda_runtime.h>
#include <cuda_bf16.h>

#define BATCH 512
#define NIN   64
#define ADIM  64

typedef unsigned long long ull;

// ---------------- device scratch (static, no allocation) -------------------
__device__ float4 g_W4[63 * 2 * 1024];   // W_i^c fp32 row-major [i][c][a][k]
__device__ float4 g_P4[31 * 4 * 1024];   // pair products, row-major fp32 [mat][a*16+q]
__device__ uint4  g_Q4[248 * 512];       // quads(240)+triples(8), bf16, chunk layout:
                                         //   mat*512 + q*64 + row ; uint4 = row's k=8q..8q+7

#define AST4 17                          // A row stride in float4 units (68 floats)

// ---- packed f32x2 helpers (sm_103a) ---------------------------------------
__device__ __forceinline__ void ffma2(ull& d, ull a, ull b) {
    asm("fma.rn.f32x2 %0, %1, %2, %0;" : "+l"(d) : "l"(a), "l"(b));
}
__device__ __forceinline__ ull pk2(float x, float y) {
    ull r; asm("mov.b64 %0, {%1, %2};" : "=l"(r) : "f"(x), "f"(y)); return r;
}
__device__ __forceinline__ void up2(ull v, float& x, float& y) {
    asm("mov.b64 {%0, %1}, %2;" : "=f"(x), "=f"(y) : "l"(v));
}
__device__ __forceinline__ float tanh_ap(float x) {
    float r; asm("tanh.approx.f32 %0, %1;" : "=f"(r) : "f"(x)); return r;
}
__device__ __forceinline__ unsigned pkbf2(float x, float y) {
    __nv_bfloat162 p = __floats2bfloat162_rn(x, y);
    return *reinterpret_cast<unsigned*>(&p);
}

// Half-GEMM: thread (a, seg 0..3) computes C[a][h*32 + seg*8 .. +7].
// A padded f4 smem (stride AST4), B half-tile row-major 8 f4 per row.
__device__ __forceinline__ void gemm_half(const float4* sA4, const float4* sB4,
                                          int a, int seg, float* out8) {
    ull c0 = 0, c1 = 0, c2 = 0, c3 = 0;
    const float4* ap = sA4 + a * AST4;
    const ull*    bp = reinterpret_cast<const ull*>(sB4 + seg * 2);
    #pragma unroll
    for (int j4 = 0; j4 < 16; ++j4) {
        float4 av = ap[j4];
        #pragma unroll
        for (int jj = 0; jj < 4; ++jj) {
            float s = (jj == 0) ? av.x : (jj == 1) ? av.y : (jj == 2) ? av.z : av.w;
            ull ss = pk2(s, s);
            const ull* br = bp + (j4 * 4 + jj) * 16;   // row stride = 8 f4 = 16 u64
            ffma2(c0, ss, br[0]);
            ffma2(c1, ss, br[1]);
            ffma2(c2, ss, br[2]);
            ffma2(c3, ss, br[3]);
        }
    }
    up2(c0, out8[0], out8[1]);
    up2(c1, out8[2], out8[3]);
    up2(c2, out8[4], out8[5]);
    up2(c3, out8[6], out8[7]);
}

// ---------------------------------------------------------------------------
// Kernel 1: k_sig — every sigmoid exactly once (1 MUFU via tanh.approx).
// CTA (i, quarter q). W^1 = s*expa[k], W^0 = expa[k]-W^1. grid=252, block=256.
// ---------------------------------------------------------------------------
__global__ void __launch_bounds__(256) k_sig(const float* __restrict__ theta,
                                             const float* __restrict__ u) {
    __shared__ float expa[64];
    int blk = blockIdx.x, tid = threadIdx.x;
    int i = blk >> 2, q = blk & 3;

    if (tid < 32) {                              // softmax(u[i])
        float u0 = u[i * 64 + tid], u1 = u[i * 64 + 32 + tid];
        float mm = fmaxf(u0, u1);
        #pragma unroll
        for (int o = 16; o; o >>= 1) mm = fmaxf(mm, __shfl_xor_sync(0xffffffffu, mm, o));
        float ss = __expf(u0 - mm) + __expf(u1 - mm);
        #pragma unroll
        for (int o = 16; o; o >>= 1) ss += __shfl_xor_sync(0xffffffffu, ss, o);
        float lse = mm + __logf(ss);
        expa[tid]      = __expf(u0 - lse);
        expa[tid + 32] = __expf(u1 - lse);
    }
    __syncthreads();

    int idx4 = q * 256 + tid;
    int k0 = (idx4 * 4) & 63;
    float4 t4 = reinterpret_cast<const float4*>(theta)[i * 1024 + idx4];
    float s0 = fmaf(0.5f, tanh_ap(0.5f * t4.x), 0.5f);
    float s1 = fmaf(0.5f, tanh_ap(0.5f * t4.y), 0.5f);
    float s2 = fmaf(0.5f, tanh_ap(0.5f * t4.z), 0.5f);
    float s3 = fmaf(0.5f, tanh_ap(0.5f * t4.w), 0.5f);
    float e0 = expa[k0], e1 = expa[k0 + 1], e2 = expa[k0 + 2], e3 = expa[k0 + 3];
    float4 w1 = make_float4(s0 * e0, s1 * e1, s2 * e2, s3 * e3);
    float4 w0 = make_float4(e0 - w1.x, e1 - w1.y, e2 - w1.z, e3 - w1.w);
    g_W4[(i * 2 + 1) * 1024 + idx4] = w1;
    g_W4[(i * 2 + 0) * 1024 + idx4] = w0;
}

// ---------------------------------------------------------------------------
// Kernel 2: pairs P = W_{2t}^{c0} @ W_{2t+1}^{c1}, half-split for load balance.
// blk = pm*2 + h ; CTA computes output columns [32h, 32h+32). grid=248, block=256.
// ---------------------------------------------------------------------------
__global__ void __launch_bounds__(256) k_pair() {
    __shared__ __align__(16) float sA[64 * AST4 * 4];
    __shared__ __align__(16) float sB[2048];

    int blk = blockIdx.x, tid = threadIdx.x;
    int pm = blk >> 1, h = blk & 1;
    int t = pm >> 2, vv = pm & 3;
    const float4* A4 = g_W4 + ((2 * t)     * 2 + (vv >> 1)) * 1024;
    const float4* B4 = g_W4 + ((2 * t + 1) * 2 + (vv & 1))  * 1024;

    float4* sA4 = reinterpret_cast<float4*>(sA);
    float4* sB4 = reinterpret_cast<float4*>(sB);
    #pragma unroll
    for (int r = 0; r < 4; ++r) {
        int idx4 = tid + 256 * r;                // full A: 1024 f4
        int row = idx4 >> 4, q = idx4 & 15;
        sA4[row * AST4 + q] = A4[idx4];
    }
    #pragma unroll
    for (int r = 0; r < 2; ++r) {
        int idx = tid + 256 * r;                 // half B: 512 f4 (8 per row)
        int row = idx >> 3, q = idx & 7;
        sB4[idx] = B4[row * 16 + h * 8 + q];
    }
    __syncthreads();

    int a = tid & 63, seg = tid >> 6;            // seg 0..3
    float acc[8];
    gemm_half(sA4, sB4, a, seg, acc);

    float4* C4 = g_P4 + pm * 1024;
    C4[a * 16 + h * 8 + seg * 2]     = make_float4(acc[0], acc[1], acc[2], acc[3]);
    C4[a * 16 + h * 8 + seg * 2 + 1] = make_float4(acc[4], acc[5], acc[6], acc[7]);
}

// ---------------------------------------------------------------------------
// Kernel 3: quads/triples, half-split. blk = qm*2 + h.
// qm<240: Q = P_{2t}^{v>>2} @ P_{2t+1}^{v&3}; qm 240..247: T = P_30^{v>>1} @ W62^{v&1}.
// Output bf16 chunk layout. grid = 496, block = 256.
// ---------------------------------------------------------------------------
__global__ void __launch_bounds__(256) k_quad() {
    __shared__ __align__(16) float sA[64 * AST4 * 4];
    __shared__ __align__(16) float sB[2048];
    int blk = blockIdx.x, tid = threadIdx.x;
    int qm = blk >> 1, h = blk & 1;

    const float4 *A4, *B4;
    if (qm < 240) {
        int t = qm >> 4, v = qm & 15;
        A4 = g_P4 + ((2 * t)     * 4 + (v >> 2)) * 1024;
        B4 = g_P4 + ((2 * t + 1) * 4 + (v & 3))  * 1024;
    } else {
        int v = qm - 240;
        A4 = g_P4 + (30 * 4 + (v >> 1)) * 1024;
        B4 = g_W4 + (62 * 2 + (v & 1)) * 1024;
    }

    float4* sA4 = reinterpret_cast<float4*>(sA);
    float4* sB4 = reinterpret_cast<float4*>(sB);
    #pragma unroll
    for (int r = 0; r < 4; ++r) {
        int idx4 = tid + 256 * r;
        int row = idx4 >> 4, q = idx4 & 15;
        sA4[row * AST4 + q] = A4[idx4];
    }
    #pragma unroll
    for (int r = 0; r < 2; ++r) {
        int idx = tid + 256 * r;
        int row = idx >> 3, q = idx & 7;
        sB4[idx] = B4[row * 16 + h * 8 + q];
    }
    __syncthreads();

    int a = tid & 63, seg = tid >> 6;
    float acc[8];
    gemm_half(sA4, sB4, a, seg, acc);

    // thread's 8 cols = k in [h*32+seg*8, +8) = chunk (h*4+seg)
    uint4 uo;
    uo.x = pkbf2(acc[0], acc[1]);
    uo.y = pkbf2(acc[2], acc[3]);
    uo.z = pkbf2(acc[4], acc[5]);
    uo.w = pkbf2(acc[6], acc[7]);
    g_Q4[qm * 512 + (h * 4 + seg) * 64 + a] = uo;
}

// ---------------------------------------------------------------------------
// Kernel 4: log-semiring chain, 16 steps, bf16 weights.
// 256 threads per batch: thread = (row a = tid>>2, k-quarter hk = tid&3),
// 16-wide partial dots combined intra-warp (shfl 1,2). Max refreshed EVERY
// step via warp-local scaling (8 warp maxes in smem, per-group rescale),
// ONE barrier per step, double-buffered se/red. grid = 512, block = 256.
// ---------------------------------------------------------------------------
__device__ __forceinline__ int matq(unsigned long long bits, int t) {
    unsigned nib = (unsigned)(bits >> (4 * t)) & 0xFu;
    unsigned v = ((nib & 1u) << 3) | ((nib & 2u) << 1) | ((nib & 4u) >> 1) | ((nib & 8u) >> 3);
    return t * 16 + (int)v;
}

__global__ void __launch_bounds__(256) k_main(const float* __restrict__ x,
                                              const float* __restrict__ theta,
                                              float* __restrict__ out) {
    int tid = threadIdx.x;
    int a = tid >> 2, hk = tid & 3;
    int w = tid >> 5;
    int b = blockIdx.x;

    __shared__ __align__(16) float se[2][64];
    __shared__ float red[2][8];
    __shared__ unsigned sb[2];

    if (tid < 64) {
        float xa = x[b * 64 + tid];
        unsigned bal = __ballot_sync(0xffffffffu, xa != 0.0f);
        if ((tid & 31) == 0) sb[tid >> 5] = bal;
    }
    __syncthreads();
    ull bits = ((ull)sb[1] << 32) | (ull)sb[0];

    // v init: log p(x63 | a, col 0)  (same value on all 4 lanes of row a)
    int c63 = (int)(bits >> 63) & 1;
    float t63 = theta[63 * 4096 + a * 64];
    float v = (c63 ? t63 : 0.0f) - fmaxf(t63, 0.0f)
            - __logf(1.0f + __expf(-fabsf(t63)));

    int m0 = 240 + (((int)(bits >> 60) & 1) << 2)
                 + (((int)(bits >> 61) & 1) << 1)
                 +  ((int)(bits >> 62) & 1);

    #pragma unroll 1
    for (int s = 0; s < 16; ++s) {
        int mat = (s == 0) ? m0 : matq(bits, 15 - s);   // triple, then t=14..0
        const uint4* base = g_Q4 + mat * 512;
        // this thread's 16 weights: chunks 2hk, 2hk+1 of row a
        uint4 w0 = base[(2 * hk)     * 64 + a];
        uint4 w1 = base[(2 * hk + 1) * 64 + a];

        int pb = s & 1;
        // warp max over its 8 rows (lane = (a&7)*4 + hk; row bits at lane bits 2..4)
        float wm = v;
        wm = fmaxf(wm, __shfl_xor_sync(0xffffffffu, wm, 4));
        wm = fmaxf(wm, __shfl_xor_sync(0xffffffffu, wm, 8));
        wm = fmaxf(wm, __shfl_xor_sync(0xffffffffu, wm, 16));
        if ((tid & 31) == 0) red[pb][w] = wm;
        if (hk == 0) se[pb][a] = __expf(v - wm);        // warp-local scale
        __syncthreads();

        float m = red[pb][0];
        #pragma unroll
        for (int i = 1; i < 8; ++i) m = fmaxf(m, red[pb][i]);
        // columns [16hk,16hk+8) come from rows owned by warp 2hk; next 8 from 2hk+1
        float s0 = __expf(red[pb][2 * hk]     - m);
        float s1 = __expf(red[pb][2 * hk + 1] - m);

        const float4* e4 = reinterpret_cast<const float4*>(se[pb]) + 4 * hk;
        float4 ea = e4[0], eb = e4[1], ec = e4[2], ed = e4[3];

        float a0, a1, a2, a3, b0, b1, b2, b3;
        a0 = __uint_as_float(w0.x << 16)         * ea.x;
        a1 = __uint_as_float(w0.x & 0xffff0000u) * ea.y;
        a2 = __uint_as_float(w0.y << 16)         * ea.z;
        a3 = __uint_as_float(w0.y & 0xffff0000u) * ea.w;
        a0 = fmaf(__uint_as_float(w0.z << 16),         eb.x, a0);
        a1 = fmaf(__uint_as_float(w0.z & 0xffff0000u), eb.y, a1);
        a2 = fmaf(__uint_as_float(w0.w << 16),         eb.z, a2);
        a3 = fmaf(__uint_as_float(w0.w & 0xffff0000u), eb.w, a3);
        b0 = __uint_as_float(w1.x << 16)         * ec.x;
        b1 = __uint_as_float(w1.x & 0xffff0000u) * ec.y;
        b2 = __uint_as_float(w1.y << 16)         * ec.z;
        b3 = __uint_as_float(w1.y & 0xffff0000u) * ec.w;
        b0 = fmaf(__uint_as_float(w1.z << 16),         ed.x, b0);
        b1 = fmaf(__uint_as_float(w1.z & 0xffff0000u), ed.y, b1);
        b2 = fmaf(__uint_as_float(w1.w << 16),         ed.z, b2);
        b3 = fmaf(__uint_as_float(w1.w & 0xffff0000u), ed.w, b3);
        float g0 = (a0 + a1) + (a2 + a3);
        float g1 = (b0 + b1) + (b2 + b3);

        float p = fmaf(s0, g0, s1 * g1);
        // combine the 4 k-quarters (lanes a*4 + {0..3} are adjacent)
        p += __shfl_xor_sync(0xffffffffu, p, 1);
        p += __shfl_xor_sync(0xffffffffu, p, 2);
        v = __logf(p) + m;
    }

    if (hk == 0) out[b * 64 + a] = v;
}

// ---------------------------------------------------------------------------
extern "C" void kernel_launch(void* const* d_in, const int* in_sizes, int n_in,
                              void* d_out, int out_size) {
    const float* x     = nullptr;
    const float* theta = nullptr;
    const float* u     = nullptr;
    for (int i = 0; i < n_in; ++i) {
        if      (in_sizes[i] == BATCH * NIN)       x     = (const float*)d_in[i];
        else if (in_sizes[i] == NIN * ADIM * ADIM) theta = (const float*)d_in[i];
        else if (in_sizes[i] == (NIN - 1) * ADIM)  u     = (const float*)d_in[i];
    }

    k_sig <<<252, 256>>>(theta, u);
    k_pair<<<248, 256>>>();
    k_quad<<<496, 256>>>();
    k_main<<<BATCH, 256>>>(x, theta, (float*)d_out);
}

// round 16
// speedup vs baseline: 1.5234x; 1.5234x over previous
#include <cuda_runtime.h>
#include <cuda_bf16.h>

#define BATCH 512
#define NIN   64
#define ADIM  64

typedef unsigned long long ull;

// ---------------- device scratch (static, no allocation) -------------------
__device__ float4 g_W4[63 * 2 * 1024];   // W_i^c fp32 row-major [i][c][a][k]
__device__ float4 g_P4[31 * 4 * 1024];   // pair products, row-major fp32 [mat][a*16+q]
__device__ uint4  g_Q4[248 * 512];       // quads(240)+triples(8), bf16, chunk layout:
                                         //   mat*512 + q*64 + row ; uint4 = row's k=8q..8q+7

#define AST4 17                          // A row stride in float4 units (68 floats)

// ---- packed f32x2 helpers (sm_103a) ---------------------------------------
__device__ __forceinline__ void ffma2(ull& d, ull a, ull b) {
    asm("fma.rn.f32x2 %0, %1, %2, %0;" : "+l"(d) : "l"(a), "l"(b));
}
__device__ __forceinline__ ull pk2(float x, float y) {
    ull r; asm("mov.b64 %0, {%1, %2};" : "=l"(r) : "f"(x), "f"(y)); return r;
}
__device__ __forceinline__ void up2(ull v, float& x, float& y) {
    asm("mov.b64 {%0, %1}, %2;" : "=f"(x), "=f"(y) : "l"(v));
}
__device__ __forceinline__ float tanh_ap(float x) {
    float r; asm("tanh.approx.f32 %0, %1;" : "=f"(r) : "f"(x)); return r;
}
__device__ __forceinline__ unsigned pkbf2(float x, float y) {
    __nv_bfloat162 p = __floats2bfloat162_rn(x, y);
    return *reinterpret_cast<unsigned*>(&p);
}

// Half-GEMM: thread (a, seg 0..3) computes C[a][h*32 + seg*8 .. +7].
// A padded f4 smem (stride AST4), B half-tile row-major 8 f4 per row.
__device__ __forceinline__ void gemm_half(const float4* sA4, const float4* sB4,
                                          int a, int seg, float* out8) {
    ull c0 = 0, c1 = 0, c2 = 0, c3 = 0;
    const float4* ap = sA4 + a * AST4;
    const ull*    bp = reinterpret_cast<const ull*>(sB4 + seg * 2);
    #pragma unroll
    for (int j4 = 0; j4 < 16; ++j4) {
        float4 av = ap[j4];
        #pragma unroll
        for (int jj = 0; jj < 4; ++jj) {
            float s = (jj == 0) ? av.x : (jj == 1) ? av.y : (jj == 2) ? av.z : av.w;
            ull ss = pk2(s, s);
            const ull* br = bp + (j4 * 4 + jj) * 16;   // row stride = 8 f4 = 16 u64
            ffma2(c0, ss, br[0]);
            ffma2(c1, ss, br[1]);
            ffma2(c2, ss, br[2]);
            ffma2(c3, ss, br[3]);
        }
    }
    up2(c0, out8[0], out8[1]);
    up2(c1, out8[2], out8[3]);
    up2(c2, out8[4], out8[5]);
    up2(c3, out8[6], out8[7]);
}

// ---------------------------------------------------------------------------
// Kernel 1: k_sig — every sigmoid exactly once (1 MUFU via tanh.approx).
// CTA (i, quarter q). W^1 = s*expa[k], W^0 = expa[k]-W^1. grid=252, block=256.
// ---------------------------------------------------------------------------
__global__ void __launch_bounds__(256) k_sig(const float* __restrict__ theta,
                                             const float* __restrict__ u) {
    __shared__ float expa[64];
    int blk = blockIdx.x, tid = threadIdx.x;
    int i = blk >> 2, q = blk & 3;

    if (tid < 32) {                              // softmax(u[i])
        float u0 = u[i * 64 + tid], u1 = u[i * 64 + 32 + tid];
        float mm = fmaxf(u0, u1);
        #pragma unroll
        for (int o = 16; o; o >>= 1) mm = fmaxf(mm, __shfl_xor_sync(0xffffffffu, mm, o));
        float ss = __expf(u0 - mm) + __expf(u1 - mm);
        #pragma unroll
        for (int o = 16; o; o >>= 1) ss += __shfl_xor_sync(0xffffffffu, ss, o);
        float lse = mm + __logf(ss);
        expa[tid]      = __expf(u0 - lse);
        expa[tid + 32] = __expf(u1 - lse);
    }
    __syncthreads();

    int idx4 = q * 256 + tid;
    int k0 = (idx4 * 4) & 63;
    float4 t4 = reinterpret_cast<const float4*>(theta)[i * 1024 + idx4];
    float s0 = fmaf(0.5f, tanh_ap(0.5f * t4.x), 0.5f);
    float s1 = fmaf(0.5f, tanh_ap(0.5f * t4.y), 0.5f);
    float s2 = fmaf(0.5f, tanh_ap(0.5f * t4.z), 0.5f);
    float s3 = fmaf(0.5f, tanh_ap(0.5f * t4.w), 0.5f);
    float e0 = expa[k0], e1 = expa[k0 + 1], e2 = expa[k0 + 2], e3 = expa[k0 + 3];
    float4 w1 = make_float4(s0 * e0, s1 * e1, s2 * e2, s3 * e3);
    float4 w0 = make_float4(e0 - w1.x, e1 - w1.y, e2 - w1.z, e3 - w1.w);
    g_W4[(i * 2 + 1) * 1024 + idx4] = w1;
    g_W4[(i * 2 + 0) * 1024 + idx4] = w0;
}

// ---------------------------------------------------------------------------
// Kernel 2: pairs P = W_{2t}^{c0} @ W_{2t+1}^{c1}, half-split for load balance.
// blk = pm*2 + h ; CTA computes output columns [32h, 32h+32). grid=248, block=256.
// ---------------------------------------------------------------------------
__global__ void __launch_bounds__(256) k_pair() {
    __shared__ __align__(16) float sA[64 * AST4 * 4];
    __shared__ __align__(16) float sB[2048];

    int blk = blockIdx.x, tid = threadIdx.x;
    int pm = blk >> 1, h = blk & 1;
    int t = pm >> 2, vv = pm & 3;
    const float4* A4 = g_W4 + ((2 * t)     * 2 + (vv >> 1)) * 1024;
    const float4* B4 = g_W4 + ((2 * t + 1) * 2 + (vv & 1))  * 1024;

    float4* sA4 = reinterpret_cast<float4*>(sA);
    float4* sB4 = reinterpret_cast<float4*>(sB);
    #pragma unroll
    for (int r = 0; r < 4; ++r) {
        int idx4 = tid + 256 * r;                // full A: 1024 f4
        int row = idx4 >> 4, q = idx4 & 15;
        sA4[row * AST4 + q] = A4[idx4];
    }
    #pragma unroll
    for (int r = 0; r < 2; ++r) {
        int idx = tid + 256 * r;                 // half B: 512 f4 (8 per row)
        int row = idx >> 3, q = idx & 7;
        sB4[idx] = B4[row * 16 + h * 8 + q];
    }
    __syncthreads();

    int a = tid & 63, seg = tid >> 6;            // seg 0..3
    float acc[8];
    gemm_half(sA4, sB4, a, seg, acc);

    float4* C4 = g_P4 + pm * 1024;
    C4[a * 16 + h * 8 + seg * 2]     = make_float4(acc[0], acc[1], acc[2], acc[3]);
    C4[a * 16 + h * 8 + seg * 2 + 1] = make_float4(acc[4], acc[5], acc[6], acc[7]);
}

// ---------------------------------------------------------------------------
// Kernel 3: quads/triples, half-split. blk = qm*2 + h.
// qm<240: Q = P_{2t}^{v>>2} @ P_{2t+1}^{v&3}; qm 240..247: T = P_30^{v>>1} @ W62^{v&1}.
// Output bf16 chunk layout. grid = 496, block = 256.
// ---------------------------------------------------------------------------
__global__ void __launch_bounds__(256) k_quad() {
    __shared__ __align__(16) float sA[64 * AST4 * 4];
    __shared__ __align__(16) float sB[2048];
    int blk = blockIdx.x, tid = threadIdx.x;
    int qm = blk >> 1, h = blk & 1;

    const float4 *A4, *B4;
    if (qm < 240) {
        int t = qm >> 4, v = qm & 15;
        A4 = g_P4 + ((2 * t)     * 4 + (v >> 2)) * 1024;
        B4 = g_P4 + ((2 * t + 1) * 4 + (v & 3))  * 1024;
    } else {
        int v = qm - 240;
        A4 = g_P4 + (30 * 4 + (v >> 1)) * 1024;
        B4 = g_W4 + (62 * 2 + (v & 1)) * 1024;
    }

    float4* sA4 = reinterpret_cast<float4*>(sA);
    float4* sB4 = reinterpret_cast<float4*>(sB);
    #pragma unroll
    for (int r = 0; r < 4; ++r) {
        int idx4 = tid + 256 * r;
        int row = idx4 >> 4, q = idx4 & 15;
        sA4[row * AST4 + q] = A4[idx4];
    }
    #pragma unroll
    for (int r = 0; r < 2; ++r) {
        int idx = tid + 256 * r;
        int row = idx >> 3, q = idx & 7;
        sB4[idx] = B4[row * 16 + h * 8 + q];
    }
    __syncthreads();

    int a = tid & 63, seg = tid >> 6;
    float acc[8];
    gemm_half(sA4, sB4, a, seg, acc);

    // thread's 8 cols = k in [h*32+seg*8, +8) = chunk (h*4+seg)
    uint4 uo;
    uo.x = pkbf2(acc[0], acc[1]);
    uo.y = pkbf2(acc[2], acc[3]);
    uo.z = pkbf2(acc[4], acc[5]);
    uo.w = pkbf2(acc[6], acc[7]);
    g_Q4[qm * 512 + (h * 4 + seg) * 64 + a] = uo;
}

// ---------------------------------------------------------------------------
// Kernel 4: log-semiring chain, 16 steps, bf16 weights, single sync per step
// (R13 version, measured 13.8us). CTA = 64 threads = 1 batch, thread = row.
// Step 0 = triple m0; even sp>0 -> t = 15-2sp; odd sp -> t = 14-2sp.
// grid = 512, block = 64.
// ---------------------------------------------------------------------------
__device__ __forceinline__ int matq(unsigned long long bits, int t) {
    unsigned nib = (unsigned)(bits >> (4 * t)) & 0xFu;
    unsigned v = ((nib & 1u) << 3) | ((nib & 2u) << 1) | ((nib & 4u) >> 1) | ((nib & 8u) >> 3);
    return t * 16 + (int)v;
}

__device__ __forceinline__ void dotb(const uint4* wr, const float4* e4,
                                     float& lo, float& hi) {
    float a0 = 0.f, a1 = 0.f, a2 = 0.f, a3 = 0.f;
    float b0 = 0.f, b1 = 0.f, b2 = 0.f, b3 = 0.f;
    #pragma unroll
    for (int q = 0; q < 4; ++q) {
        float4 e0 = e4[2 * q], e1 = e4[2 * q + 1];
        uint4 uw = wr[q];
        a0 = fmaf(__uint_as_float(uw.x << 16),          e0.x, a0);
        a1 = fmaf(__uint_as_float(uw.x & 0xffff0000u),  e0.y, a1);
        a2 = fmaf(__uint_as_float(uw.y << 16),          e0.z, a2);
        a3 = fmaf(__uint_as_float(uw.y & 0xffff0000u),  e0.w, a3);
        a0 = fmaf(__uint_as_float(uw.z << 16),          e1.x, a0);
        a1 = fmaf(__uint_as_float(uw.z & 0xffff0000u),  e1.y, a1);
        a2 = fmaf(__uint_as_float(uw.w << 16),          e1.z, a2);
        a3 = fmaf(__uint_as_float(uw.w & 0xffff0000u),  e1.w, a3);
    }
    #pragma unroll
    for (int q = 4; q < 8; ++q) {
        float4 e0 = e4[2 * q], e1 = e4[2 * q + 1];
        uint4 uw = wr[q];
        b0 = fmaf(__uint_as_float(uw.x << 16),          e0.x, b0);
        b1 = fmaf(__uint_as_float(uw.x & 0xffff0000u),  e0.y, b1);
        b2 = fmaf(__uint_as_float(uw.y << 16),          e0.z, b2);
        b3 = fmaf(__uint_as_float(uw.y & 0xffff0000u),  e0.w, b3);
        b0 = fmaf(__uint_as_float(uw.z << 16),          e1.x, b0);
        b1 = fmaf(__uint_as_float(uw.z & 0xffff0000u),  e1.y, b1);
        b2 = fmaf(__uint_as_float(uw.w << 16),          e1.z, b2);
        b3 = fmaf(__uint_as_float(uw.w & 0xffff0000u),  e1.w, b3);
    }
    lo = (a0 + a1) + (a2 + a3);
    hi = (b0 + b1) + (b2 + b3);
}

__global__ void __launch_bounds__(64) k_main(const float* __restrict__ x,
                                             const float* __restrict__ theta,
                                             float* __restrict__ out) {
    int tid = threadIdx.x, w = tid >> 5, l = tid & 31;
    int b = blockIdx.x;

    __shared__ __align__(16) float se[2][64];
    __shared__ float red[2];
    __shared__ unsigned sbits[2];

    float xa = x[b * 64 + tid];
    unsigned bal = __ballot_sync(0xffffffffu, xa != 0.0f);
    if (l == 0) sbits[w] = bal;
    __syncthreads();
    unsigned long long bits =
        ((unsigned long long)sbits[1] << 32) | (unsigned long long)sbits[0];

    // v init: log p(x63 | a, col 0)
    int c63 = (int)(bits >> 63) & 1;
    float t63 = theta[63 * 4096 + tid * 64];
    float v = (c63 ? t63 : 0.0f) - fmaxf(t63, 0.0f)
            - __logf(1.0f + __expf(-fabsf(t63)));

    int m0 = 240 + (((int)(bits >> 60) & 1) << 2)
                 + (((int)(bits >> 61) & 1) << 1)
                 +  ((int)(bits >> 62) & 1);

    float m = 0.0f;
    uint4 wr[8];

    #pragma unroll 1
    for (int sp = 0; sp < 8; ++sp) {
        // ---- even step: refresh max (warp-local scaling), 1 sync ----
        {
            int mat = (sp == 0) ? m0 : matq(bits, 15 - 2 * sp);   // t=13,11,...,1
            const uint4* base = g_Q4 + mat * 512;
            #pragma unroll
            for (int q = 0; q < 8; ++q) wr[q] = base[q * 64 + tid];  // issue early

            float wm = v;
            #pragma unroll
            for (int o = 16; o; o >>= 1) wm = fmaxf(wm, __shfl_xor_sync(0xffffffffu, wm, o));
            if (l == 0) red[w] = wm;
            se[0][tid] = __expf(v - wm);          // warp-local scale
            __syncthreads();
            m = fmaxf(red[0], red[1]);
            float s0 = __expf(red[0] - m);
            float s1 = __expf(red[1] - m);
            float lo, hi;
            dotb(wr, reinterpret_cast<const float4*>(se[0]), lo, hi);
            v = __logf(fmaf(s0, lo, s1 * hi)) + m;
        }
        // ---- odd step: stale max, 1 sync ----
        {
            int mat = matq(bits, 14 - 2 * sp);    // t=14,12,...,0
            const uint4* base = g_Q4 + mat * 512;
            #pragma unroll
            for (int q = 0; q < 8; ++q) wr[q] = base[q * 64 + tid];

            se[1][tid] = __expf(v - m);
            __syncthreads();
            float lo, hi;
            dotb(wr, reinterpret_cast<const float4*>(se[1]), lo, hi);
            v = __logf(lo + hi) + m;
        }
    }

    out[b * 64 + tid] = v;
}

// ---------------------------------------------------------------------------
extern "C" void kernel_launch(void* const* d_in, const int* in_sizes, int n_in,
                              void* d_out, int out_size) {
    const float* x     = nullptr;
    const float* theta = nullptr;
    const float* u     = nullptr;
    for (int i = 0; i < n_in; ++i) {
        if      (in_sizes[i] == BATCH * NIN)       x     = (const float*)d_in[i];
        else if (in_sizes[i] == NIN * ADIM * ADIM) theta = (const float*)d_in[i];
        else if (in_sizes[i] == (NIN - 1) * ADIM)  u     = (const float*)d_in[i];
    }

    k_sig <<<252, 256>>>(theta, u);
    k_pair<<<248, 256>>>();
    k_quad<<<496, 256>>>();
    k_main<<<BATCH, 64>>>(x, theta, (float*)d_out);
}

// round 17
// speedup vs baseline: 1.5377x; 1.0094x over previous
#include <cuda_runtime.h>
#include <cuda_bf16.h>

#define BATCH 512
#define NIN   64
#define ADIM  64

typedef unsigned long long ull;

// ---------------- device scratch (static, no allocation) -------------------
__device__ float4 g_W4[63 * 2 * 1024];   // W_i^c fp32 row-major [i][c][a][k]
__device__ float4 g_P4[31 * 4 * 1024];   // pair products, row-major fp32 [mat][a*16+q]
__device__ uint4  g_Q4[248 * 512];       // quads(240)+triples(8), bf16, chunk layout:
                                         //   mat*512 + q*64 + row ; uint4 = row's k=8q..8q+7

#define AST4 17                          // A row stride in float4 units (68 floats)

// ---- packed f32x2 helpers (sm_103a) ---------------------------------------
__device__ __forceinline__ void ffma2(ull& d, ull a, ull b) {
    asm("fma.rn.f32x2 %0, %1, %2, %0;" : "+l"(d) : "l"(a), "l"(b));
}
__device__ __forceinline__ ull pk2(float x, float y) {
    ull r; asm("mov.b64 %0, {%1, %2};" : "=l"(r) : "f"(x), "f"(y)); return r;
}
__device__ __forceinline__ void up2(ull v, float& x, float& y) {
    asm("mov.b64 {%0, %1}, %2;" : "=f"(x), "=f"(y) : "l"(v));
}
__device__ __forceinline__ float tanh_ap(float x) {
    float r; asm("tanh.approx.f32 %0, %1;" : "=f"(r) : "f"(x)); return r;
}
__device__ __forceinline__ unsigned pkbf2(float x, float y) {
    __nv_bfloat162 p = __floats2bfloat162_rn(x, y);
    return *reinterpret_cast<unsigned*>(&p);
}

// Half-GEMM: thread (a, seg 0..3) computes C[a][h*32 + seg*8 .. +7].
__device__ __forceinline__ void gemm_half(const float4* sA4, const float4* sB4,
                                          int a, int seg, float* out8) {
    ull c0 = 0, c1 = 0, c2 = 0, c3 = 0;
    const float4* ap = sA4 + a * AST4;
    const ull*    bp = reinterpret_cast<const ull*>(sB4 + seg * 2);
    #pragma unroll
    for (int j4 = 0; j4 < 16; ++j4) {
        float4 av = ap[j4];
        #pragma unroll
        for (int jj = 0; jj < 4; ++jj) {
            float s = (jj == 0) ? av.x : (jj == 1) ? av.y : (jj == 2) ? av.z : av.w;
            ull ss = pk2(s, s);
            const ull* br = bp + (j4 * 4 + jj) * 16;   // row stride = 8 f4 = 16 u64
            ffma2(c0, ss, br[0]);
            ffma2(c1, ss, br[1]);
            ffma2(c2, ss, br[2]);
            ffma2(c3, ss, br[3]);
        }
    }
    up2(c0, out8[0], out8[1]);
    up2(c1, out8[2], out8[3]);
    up2(c2, out8[4], out8[5]);
    up2(c3, out8[6], out8[7]);
}

// ---------------------------------------------------------------------------
// Kernel 1: k_sig — every sigmoid exactly once (1 MUFU via tanh.approx).
// grid=252, block=256.
// ---------------------------------------------------------------------------
__global__ void __launch_bounds__(256) k_sig(const float* __restrict__ theta,
                                             const float* __restrict__ u) {
    __shared__ float expa[64];
    int blk = blockIdx.x, tid = threadIdx.x;
    int i = blk >> 2, q = blk & 3;

    if (tid < 32) {                              // softmax(u[i])
        float u0 = u[i * 64 + tid], u1 = u[i * 64 + 32 + tid];
        float mm = fmaxf(u0, u1);
        #pragma unroll
        for (int o = 16; o; o >>= 1) mm = fmaxf(mm, __shfl_xor_sync(0xffffffffu, mm, o));
        float ss = __expf(u0 - mm) + __expf(u1 - mm);
        #pragma unroll
        for (int o = 16; o; o >>= 1) ss += __shfl_xor_sync(0xffffffffu, ss, o);
        float lse = mm + __logf(ss);
        expa[tid]      = __expf(u0 - lse);
        expa[tid + 32] = __expf(u1 - lse);
    }
    __syncthreads();

    int idx4 = q * 256 + tid;
    int k0 = (idx4 * 4) & 63;
    float4 t4 = reinterpret_cast<const float4*>(theta)[i * 1024 + idx4];
    float s0 = fmaf(0.5f, tanh_ap(0.5f * t4.x), 0.5f);
    float s1 = fmaf(0.5f, tanh_ap(0.5f * t4.y), 0.5f);
    float s2 = fmaf(0.5f, tanh_ap(0.5f * t4.z), 0.5f);
    float s3 = fmaf(0.5f, tanh_ap(0.5f * t4.w), 0.5f);
    float e0 = expa[k0], e1 = expa[k0 + 1], e2 = expa[k0 + 2], e3 = expa[k0 + 3];
    float4 w1 = make_float4(s0 * e0, s1 * e1, s2 * e2, s3 * e3);
    float4 w0 = make_float4(e0 - w1.x, e1 - w1.y, e2 - w1.z, e3 - w1.w);
    g_W4[(i * 2 + 1) * 1024 + idx4] = w1;
    g_W4[(i * 2 + 0) * 1024 + idx4] = w0;
}

// ---------------------------------------------------------------------------
// Kernel 2: pairs P = W_{2t}^{c0} @ W_{2t+1}^{c1}, half-split.
// blk = pm*2 + h ; CTA computes output columns [32h, 32h+32). grid=248, block=256.
// ---------------------------------------------------------------------------
__global__ void __launch_bounds__(256) k_pair() {
    __shared__ __align__(16) float sA[64 * AST4 * 4];
    __shared__ __align__(16) float sB[2048];

    int blk = blockIdx.x, tid = threadIdx.x;
    int pm = blk >> 1, h = blk & 1;
    int t = pm >> 2, vv = pm & 3;
    const float4* A4 = g_W4 + ((2 * t)     * 2 + (vv >> 1)) * 1024;
    const float4* B4 = g_W4 + ((2 * t + 1) * 2 + (vv & 1))  * 1024;

    float4* sA4 = reinterpret_cast<float4*>(sA);
    float4* sB4 = reinterpret_cast<float4*>(sB);
    #pragma unroll
    for (int r = 0; r < 4; ++r) {
        int idx4 = tid + 256 * r;                // full A: 1024 f4
        int row = idx4 >> 4, q = idx4 & 15;
        sA4[row * AST4 + q] = A4[idx4];
    }
    #pragma unroll
    for (int r = 0; r < 2; ++r) {
        int idx = tid + 256 * r;                 // half B: 512 f4 (8 per row)
        int row = idx >> 3, q = idx & 7;
        sB4[idx] = B4[row * 16 + h * 8 + q];
    }
    __syncthreads();

    int a = tid & 63, seg = tid >> 6;            // seg 0..3
    float acc[8];
    gemm_half(sA4, sB4, a, seg, acc);

    float4* C4 = g_P4 + pm * 1024;
    C4[a * 16 + h * 8 + seg * 2]     = make_float4(acc[0], acc[1], acc[2], acc[3]);
    C4[a * 16 + h * 8 + seg * 2 + 1] = make_float4(acc[4], acc[5], acc[6], acc[7]);
}

// ---------------------------------------------------------------------------
// Kernel 3: quads/triples, half-split. blk = qm*2 + h. grid=496, block=256.
// ---------------------------------------------------------------------------
__global__ void __launch_bounds__(256) k_quad() {
    __shared__ __align__(16) float sA[64 * AST4 * 4];
    __shared__ __align__(16) float sB[2048];
    int blk = blockIdx.x, tid = threadIdx.x;
    int qm = blk >> 1, h = blk & 1;

    const float4 *A4, *B4;
    if (qm < 240) {
        int t = qm >> 4, v = qm & 15;
        A4 = g_P4 + ((2 * t)     * 4 + (v >> 2)) * 1024;
        B4 = g_P4 + ((2 * t + 1) * 4 + (v & 3))  * 1024;
    } else {
        int v = qm - 240;
        A4 = g_P4 + (30 * 4 + (v >> 1)) * 1024;
        B4 = g_W4 + (62 * 2 + (v & 1)) * 1024;
    }

    float4* sA4 = reinterpret_cast<float4*>(sA);
    float4* sB4 = reinterpret_cast<float4*>(sB);
    #pragma unroll
    for (int r = 0; r < 4; ++r) {
        int idx4 = tid + 256 * r;
        int row = idx4 >> 4, q = idx4 & 15;
        sA4[row * AST4 + q] = A4[idx4];
    }
    #pragma unroll
    for (int r = 0; r < 2; ++r) {
        int idx = tid + 256 * r;
        int row = idx >> 3, q = idx & 7;
        sB4[idx] = B4[row * 16 + h * 8 + q];
    }
    __syncthreads();

    int a = tid & 63, seg = tid >> 6;
    float acc[8];
    gemm_half(sA4, sB4, a, seg, acc);

    uint4 uo;
    uo.x = pkbf2(acc[0], acc[1]);
    uo.y = pkbf2(acc[2], acc[3]);
    uo.z = pkbf2(acc[4], acc[5]);
    uo.w = pkbf2(acc[6], acc[7]);
    g_Q4[qm * 512 + (h * 4 + seg) * 64 + a] = uo;
}

// ---------------------------------------------------------------------------
// Kernel 4: log-semiring chain, 16 steps, bf16 weights, PIPELINED STALE MAX:
// scale bound m at step s = max(v) from step s-2 (valid: row sums < 1 =>
// max(v) monotonically non-increasing). The warp-max shuffle chain of the
// current v is started each step but consumed two steps later, so it runs in
// the shadow of the dot — the per-step critical path is exp -> bar -> dot -> log.
// Weights prefetched one step ahead. grid = 512, block = 64.
// ---------------------------------------------------------------------------
__device__ __forceinline__ int matq(unsigned long long bits, int t) {
    unsigned nib = (unsigned)(bits >> (4 * t)) & 0xFu;
    unsigned v = ((nib & 1u) << 3) | ((nib & 2u) << 1) | ((nib & 4u) >> 1) | ((nib & 8u) >> 3);
    return t * 16 + (int)v;
}

__device__ __forceinline__ float dotb1(const uint4* wr, const float4* e4) {
    float a0 = 0.f, a1 = 0.f, a2 = 0.f, a3 = 0.f;
    float b0 = 0.f, b1 = 0.f, b2 = 0.f, b3 = 0.f;
    #pragma unroll
    for (int q = 0; q < 4; ++q) {
        float4 e0 = e4[2 * q], e1 = e4[2 * q + 1];
        uint4 uw = wr[q];
        a0 = fmaf(__uint_as_float(uw.x << 16),          e0.x, a0);
        a1 = fmaf(__uint_as_float(uw.x & 0xffff0000u),  e0.y, a1);
        a2 = fmaf(__uint_as_float(uw.y << 16),          e0.z, a2);
        a3 = fmaf(__uint_as_float(uw.y & 0xffff0000u),  e0.w, a3);
        a0 = fmaf(__uint_as_float(uw.z << 16),          e1.x, a0);
        a1 = fmaf(__uint_as_float(uw.z & 0xffff0000u),  e1.y, a1);
        a2 = fmaf(__uint_as_float(uw.w << 16),          e1.z, a2);
        a3 = fmaf(__uint_as_float(uw.w & 0xffff0000u),  e1.w, a3);
    }
    #pragma unroll
    for (int q = 4; q < 8; ++q) {
        float4 e0 = e4[2 * q], e1 = e4[2 * q + 1];
        uint4 uw = wr[q];
        b0 = fmaf(__uint_as_float(uw.x << 16),          e0.x, b0);
        b1 = fmaf(__uint_as_float(uw.x & 0xffff0000u),  e0.y, b1);
        b2 = fmaf(__uint_as_float(uw.y << 16),          e0.z, b2);
        b3 = fmaf(__uint_as_float(uw.y & 0xffff0000u),  e0.w, b3);
        b0 = fmaf(__uint_as_float(uw.z << 16),          e1.x, b0);
        b1 = fmaf(__uint_as_float(uw.z & 0xffff0000u),  e1.y, b1);
        b2 = fmaf(__uint_as_float(uw.w << 16),          e1.z, b2);
        b3 = fmaf(__uint_as_float(uw.w & 0xffff0000u),  e1.w, b3);
    }
    return ((a0 + a1) + (a2 + a3)) + ((b0 + b1) + (b2 + b3));
}

__global__ void __launch_bounds__(64) k_main(const float* __restrict__ x,
                                             const float* __restrict__ theta,
                                             float* __restrict__ out) {
    int tid = threadIdx.x, w = tid >> 5, l = tid & 31;
    int b = blockIdx.x;

    __shared__ __align__(16) float se[2][64];
    __shared__ float red[2][2];
    __shared__ unsigned sbits[2];

    float xa = x[b * 64 + tid];
    unsigned bal = __ballot_sync(0xffffffffu, xa != 0.0f);
    if (l == 0) sbits[w] = bal;
    __syncthreads();
    unsigned long long bits =
        ((unsigned long long)sbits[1] << 32) | (unsigned long long)sbits[0];

    // v init: log p(x63 | a, col 0)  (all entries <= 0)
    int c63 = (int)(bits >> 63) & 1;
    float t63 = theta[63 * 4096 + tid * 64];
    float v = (c63 ? t63 : 0.0f) - fmaxf(t63, 0.0f)
            - __logf(1.0f + __expf(-fabsf(t63)));

    int m0 = 240 + (((int)(bits >> 60) & 1) << 2)
                 + (((int)(bits >> 61) & 1) << 1)
                 +  ((int)(bits >> 62) & 1);

    // prefetch step 0 (triple)
    uint4 wrA[8], wrB[8];
    {
        const uint4* base = g_Q4 + m0 * 512;
        #pragma unroll
        for (int q = 0; q < 8; ++q) wrA[q] = base[q * 64 + tid];
    }

    float m = 0.0f;          // stale global bound (max of v two steps ago)
    float wm_prev = 0.0f;    // warp max of v one step older than current

    #pragma unroll 1
    for (int sp = 0; sp < 8; ++sp) {
        // ---- even step s=2sp: compute with wrA, prefetch wrB ----
        {
            const uint4* nb = g_Q4 + matq(bits, 14 - 2 * sp) * 512;  // step s+1
            #pragma unroll
            for (int q = 0; q < 8; ++q) wrB[q] = nb[q * 64 + tid];

            if (l == 0) red[0][w] = wm_prev;      // warp max of v_{s-2}
            se[0][tid] = __expf(v - m);
            float wm = v;                         // shadow chain for step s+2
            #pragma unroll
            for (int o = 16; o; o >>= 1) wm = fmaxf(wm, __shfl_xor_sync(0xffffffffu, wm, o));
            __syncthreads();
            float m_next = fmaxf(red[0][0], red[0][1]);
            v = __logf(dotb1(wrA, reinterpret_cast<const float4*>(se[0]))) + m;
            m = m_next;
            wm_prev = wm;
        }
        // ---- odd step s=2sp+1: compute with wrB, prefetch wrA ----
        {
            if (sp < 7) {
                const uint4* nb = g_Q4 + matq(bits, 13 - 2 * sp) * 512;  // step s+1
                #pragma unroll
                for (int q = 0; q < 8; ++q) wrA[q] = nb[q * 64 + tid];
            }
            if (l == 0) red[1][w] = wm_prev;
            se[1][tid] = __expf(v - m);
            float wm = v;
            #pragma unroll
            for (int o = 16; o; o >>= 1) wm = fmaxf(wm, __shfl_xor_sync(0xffffffffu, wm, o));
            __syncthreads();
            float m_next = fmaxf(red[1][0], red[1][1]);
            v = __logf(dotb1(wrB, reinterpret_cast<const float4*>(se[1]))) + m;
            m = m_next;
            wm_prev = wm;
        }
    }

    out[b * 64 + tid] = v;
}

// ---------------------------------------------------------------------------
extern "C" void kernel_launch(void* const* d_in, const int* in_sizes, int n_in,
                              void* d_out, int out_size) {
    const float* x     = nullptr;
    const float* theta = nullptr;
    const float* u     = nullptr;
    for (int i = 0; i < n_in; ++i) {
        if      (in_sizes[i] == BATCH * NIN)       x     = (const float*)d_in[i];
        else if (in_sizes[i] == NIN * ADIM * ADIM) theta = (const float*)d_in[i];
        else if (in_sizes[i] == (NIN - 1) * ADIM)  u     = (const float*)d_in[i];
    }

    k_sig <<<252, 256>>>(theta, u);
    k_pair<<<248, 256>>>();
    k_quad<<<496, 256>>>();
    k_main<<<BATCH, 64>>>(x, theta, (float*)d_out);
}